// round 1
// baseline (speedup 1.0000x reference)
#include <cuda_runtime.h>

#define NN 50000
#define D  128
#define NE 800000
#define NL 200000

// ---------------- scratch (device globals; no allocation allowed) ----------
__device__ float g_h0[NN * D];
__device__ float g_agg[NN * D];
__device__ float g_h1[NN * D];
__device__ float g_h2[NN * D];
__device__ float g_deg[NN];
__device__ float g_inv[NN];

// ---------------- h0 = concat(emb[n_id], x_struct) -------------------------
__global__ void k_concat(const int* __restrict__ n_id,
                         const float* __restrict__ x,
                         const float* __restrict__ emb) {
    int t = blockIdx.x * blockDim.x + threadIdx.x;
    if (t >= NN * 32) return;
    int i = t >> 5;        // node
    int q = t & 31;        // float4 quad within 128-wide row
    float4 v;
    if (q < 16) v = *(const float4*)&emb[(long)n_id[i] * 64 + q * 4];
    else        v = *(const float4*)&x[(long)i * 64 + (q - 16) * 4];
    *(float4*)&g_h0[(long)i * 128 + q * 4] = v;
}

// ---------------- degree + inverse degree ----------------------------------
__global__ void k_deg(const int* __restrict__ dst) {
    int e = blockIdx.x * blockDim.x + threadIdx.x;
    if (e < NE) atomicAdd(&g_deg[dst[e]], 1.0f);
}

__global__ void k_invdeg() {
    int i = blockIdx.x * blockDim.x + threadIdx.x;
    if (i < NN) g_inv[i] = 1.0f / fmaxf(g_deg[i], 1.0f);
}

// ---------------- scatter-add: agg[dst] += h[src] (one warp per edge) ------
__global__ void k_scatter(const float* __restrict__ h,
                          const int* __restrict__ src,
                          const int* __restrict__ dst,
                          float* __restrict__ agg) {
    int w    = (blockIdx.x * blockDim.x + threadIdx.x) >> 5;
    int lane = threadIdx.x & 31;
    if (w >= NE) return;
    int s = src[w];
    int d = dst[w];
    float4 v = *(const float4*)&h[(long)s * 128 + lane * 4];
    float* p = &agg[(long)d * 128 + lane * 4];
    atomicAdd(p + 0, v.x);
    atomicAdd(p + 1, v.y);
    atomicAdd(p + 2, v.z);
    atomicAdd(p + 3, v.w);
}

// ---------------- fused SAGE GEMM: out = (agg*inv)@Wl + h@Wr + b -----------
// A = [mean | h]  (K = 256),  W = [Wl ; Wr]  (256 x 128), all staged in smem.
// Block: 256 threads, 64 rows x 128 cols tile. Thread microtile: 8 rows x 4 cols.
__global__ void __launch_bounds__(256, 1)
k_gemm(const float* __restrict__ Agg, const float* __restrict__ Inv,
       const float* __restrict__ H,
       const float* __restrict__ Wl, const float* __restrict__ Wr,
       const float* __restrict__ bias, float* __restrict__ out, int do_relu) {
    extern __shared__ float smem[];
    float* Ws = smem;             // [256][128]  = 128 KB
    float* As = smem + 256 * 128; // [256][64]   =  64 KB (k-major, row minor)

    int tid = threadIdx.x;
    // stage W = [Wl ; Wr]
    for (int i = tid; i < 128 * 128; i += 256) {
        Ws[i]             = Wl[i];
        Ws[128 * 128 + i] = Wr[i];
    }
    // stage A panel: 64 rows x 256 k, transposed to As[k*64 + r]
    int row0 = blockIdx.x * 64;
    for (int i = tid; i < 64 * 256; i += 256) {
        int r = i & 63;
        int k = i >> 6;
        int gr = row0 + r;
        float v = 0.0f;
        if (gr < NN)
            v = (k < 128) ? Agg[(long)gr * 128 + k] * Inv[gr]
                          : H[(long)gr * 128 + (k - 128)];
        As[k * 64 + r] = v;
    }
    __syncthreads();

    int tc = tid & 31;   // column group: cols [4*tc, 4*tc+3]
    int tr = tid >> 5;   // row group:    rows [8*tr, 8*tr+7]

    float acc[8][4];
#pragma unroll
    for (int i = 0; i < 8; i++)
#pragma unroll
        for (int j = 0; j < 4; j++) acc[i][j] = 0.0f;

#pragma unroll 4
    for (int k = 0; k < 256; ++k) {
        float4 bv = *(const float4*)&Ws[k * 128 + tc * 4];
        float4 a0 = *(const float4*)&As[k * 64 + tr * 8];
        float4 a1 = *(const float4*)&As[k * 64 + tr * 8 + 4];
        float a[8] = {a0.x, a0.y, a0.z, a0.w, a1.x, a1.y, a1.z, a1.w};
#pragma unroll
        for (int i = 0; i < 8; i++) {
            acc[i][0] += a[i] * bv.x;
            acc[i][1] += a[i] * bv.y;
            acc[i][2] += a[i] * bv.z;
            acc[i][3] += a[i] * bv.w;
        }
    }

    float4 bv = *(const float4*)&bias[tc * 4];
#pragma unroll
    for (int i = 0; i < 8; i++) {
        int gr = row0 + tr * 8 + i;
        if (gr < NN) {
            float4 o;
            o.x = acc[i][0] + bv.x;
            o.y = acc[i][1] + bv.y;
            o.z = acc[i][2] + bv.z;
            o.w = acc[i][3] + bv.w;
            if (do_relu) {
                o.x = fmaxf(o.x, 0.0f);
                o.y = fmaxf(o.y, 0.0f);
                o.z = fmaxf(o.z, 0.0f);
                o.w = fmaxf(o.w, 0.0f);
            }
            *(float4*)&out[(long)gr * 128 + tc * 4] = o;
        }
    }
}

// ---------------- edge-wise dot product ------------------------------------
__global__ void k_edgedot(const float* __restrict__ h2,
                          const int* __restrict__ eli,
                          float* __restrict__ out) {
    int w    = (blockIdx.x * blockDim.x + threadIdx.x) >> 5;
    int lane = threadIdx.x & 31;
    if (w >= NL) return;
    int s = eli[w];
    int d = eli[NL + w];
    float4 a = *(const float4*)&h2[(long)s * 128 + lane * 4];
    float4 b = *(const float4*)&h2[(long)d * 128 + lane * 4];
    float sum = a.x * b.x + a.y * b.y + a.z * b.z + a.w * b.w;
#pragma unroll
    for (int o = 16; o; o >>= 1) sum += __shfl_xor_sync(0xffffffffu, sum, o);
    if (lane == 0) out[w] = sum;
}

// ---------------- launch ----------------------------------------------------
extern "C" void kernel_launch(void* const* d_in, const int* in_sizes, int n_in,
                              void* d_out, int out_size) {
    const int*   n_id = (const int*)d_in[0];
    const float* x    = (const float*)d_in[1];
    const int*   ei   = (const int*)d_in[2];   // [2, NE]: src=ei, dst=ei+NE
    const int*   eli  = (const int*)d_in[3];   // [2, NL]
    const float* emb  = (const float*)d_in[4];
    const float* W1l  = (const float*)d_in[5];
    const float* W1r  = (const float*)d_in[6];
    const float* b1   = (const float*)d_in[7];
    const float* W2l  = (const float*)d_in[8];
    const float* W2r  = (const float*)d_in[9];
    const float* b2   = (const float*)d_in[10];
    float* out = (float*)d_out;

    float *h0, *agg, *h1, *h2, *deg, *inv;
    cudaGetSymbolAddress((void**)&h0,  g_h0);
    cudaGetSymbolAddress((void**)&agg, g_agg);
    cudaGetSymbolAddress((void**)&h1,  g_h1);
    cudaGetSymbolAddress((void**)&h2,  g_h2);
    cudaGetSymbolAddress((void**)&deg, g_deg);
    cudaGetSymbolAddress((void**)&inv, g_inv);

    const int SMEM = (256 * 128 + 256 * 64) * 4;  // 192 KB
    cudaFuncSetAttribute(k_gemm, cudaFuncAttributeMaxDynamicSharedMemorySize, SMEM);

    cudaMemsetAsync(agg, 0, sizeof(float) * NN * D);
    cudaMemsetAsync(deg, 0, sizeof(float) * NN);

    k_concat<<<(NN * 32 + 255) / 256, 256>>>(n_id, x, emb);
    k_deg<<<(NE + 255) / 256, 256>>>(ei + NE);
    k_invdeg<<<(NN + 255) / 256, 256>>>();

    // layer 1
    k_scatter<<<(NE * 32 + 255) / 256, 256>>>(h0, ei, ei + NE, agg);
    k_gemm<<<(NN + 63) / 64, 256, SMEM>>>(agg, inv, h0, W1l, W1r, b1, h1, 1);

    // layer 2
    cudaMemsetAsync(agg, 0, sizeof(float) * NN * D);
    k_scatter<<<(NE * 32 + 255) / 256, 256>>>(h1, ei, ei + NE, agg);
    k_gemm<<<(NN + 63) / 64, 256, SMEM>>>(agg, inv, h1, W2l, W2r, b2, h2, 0);

    // classifier
    k_edgedot<<<(NL * 32 + 255) / 256, 256>>>(h2, eli, out);
}

// round 2
// speedup vs baseline: 2.7002x; 2.7002x over previous
#include <cuda_runtime.h>
#include <cstdint>

#define NN 50000
#define D  128
#define NE 800000
#define NL 200000

// ---------------- scratch (device globals) ----------------------------------
__device__ float g_h0[NN * D];
__device__ float g_mean[NN * D];
__device__ float g_h1[NN * D];
__device__ float g_h2[NN * D];
__device__ int   g_deg[NN];
__device__ int   g_rowptr[NN];
__device__ int   g_cursor[NN];
__device__ int   g_col[NE];
__device__ int   g_bsums[64];

// ---------------- h0 = concat(emb[n_id], x_struct) -------------------------
__global__ void k_concat(const int* __restrict__ n_id,
                         const float* __restrict__ x,
                         const float* __restrict__ emb,
                         float* __restrict__ h0) {
    int t = blockIdx.x * blockDim.x + threadIdx.x;
    if (t >= NN * 32) return;
    int i = t >> 5;
    int q = t & 31;
    float4 v;
    if (q < 16) v = *(const float4*)&emb[(long)n_id[i] * 64 + q * 4];
    else        v = *(const float4*)&x[(long)i * 64 + (q - 16) * 4];
    *(float4*)&h0[(long)i * 128 + q * 4] = v;
}

// ---------------- CSR build --------------------------------------------------
__global__ void k_deg(const int* __restrict__ dst, int* __restrict__ deg) {
    int e = blockIdx.x * blockDim.x + threadIdx.x;
    if (e < NE) atomicAdd(&deg[dst[e]], 1);
}

__global__ void k_scan1(const int* __restrict__ deg, int* __restrict__ out,
                        int* __restrict__ bsums) {
    __shared__ int sh[1024];
    int gid = blockIdx.x * 1024 + threadIdx.x;
    int v = (gid < NN) ? deg[gid] : 0;
    sh[threadIdx.x] = v;
    __syncthreads();
#pragma unroll
    for (int off = 1; off < 1024; off <<= 1) {
        int t = (threadIdx.x >= off) ? sh[threadIdx.x - off] : 0;
        __syncthreads();
        sh[threadIdx.x] += t;
        __syncthreads();
    }
    if (gid < NN) out[gid] = sh[threadIdx.x] - v;  // exclusive
    if (threadIdx.x == 1023) bsums[blockIdx.x] = sh[1023];
}

__global__ void k_scan2(int* __restrict__ bsums, int nb) {
    if (threadIdx.x == 0) {
        int acc = 0;
        for (int i = 0; i < nb; i++) { int t = bsums[i]; bsums[i] = acc; acc += t; }
    }
}

__global__ void k_scan3(int* __restrict__ out, const int* __restrict__ bsums) {
    int gid = blockIdx.x * 1024 + threadIdx.x;
    if (gid < NN) out[gid] += bsums[blockIdx.x];
}

__global__ void k_fill(const int* __restrict__ src, const int* __restrict__ dst,
                       const int* __restrict__ rowptr, int* __restrict__ cursor,
                       int* __restrict__ col) {
    int e = blockIdx.x * blockDim.x + threadIdx.x;
    if (e >= NE) return;
    int d = dst[e];
    int pos = rowptr[d] + atomicAdd(&cursor[d], 1);
    col[pos] = src[e];
}

// ---------------- mean aggregation: warp per node, atomic-free --------------
__global__ void k_agg(const float* __restrict__ h,
                      const int* __restrict__ rowptr,
                      const int* __restrict__ deg,
                      const int* __restrict__ col,
                      float* __restrict__ mean) {
    int w    = (blockIdx.x * blockDim.x + threadIdx.x) >> 5;
    int lane = threadIdx.x & 31;
    if (w >= NN) return;
    int start = rowptr[w];
    int n     = deg[w];
    float4 acc = make_float4(0.f, 0.f, 0.f, 0.f);
    int j = 0;
    for (; j + 4 <= n; j += 4) {
        int s0 = col[start + j];
        int s1 = col[start + j + 1];
        int s2 = col[start + j + 2];
        int s3 = col[start + j + 3];
        float4 v0 = *(const float4*)&h[(long)s0 * 128 + lane * 4];
        float4 v1 = *(const float4*)&h[(long)s1 * 128 + lane * 4];
        float4 v2 = *(const float4*)&h[(long)s2 * 128 + lane * 4];
        float4 v3 = *(const float4*)&h[(long)s3 * 128 + lane * 4];
        acc.x += v0.x + v1.x + v2.x + v3.x;
        acc.y += v0.y + v1.y + v2.y + v3.y;
        acc.z += v0.z + v1.z + v2.z + v3.z;
        acc.w += v0.w + v1.w + v2.w + v3.w;
    }
    for (; j < n; j++) {
        int s = col[start + j];
        float4 v = *(const float4*)&h[(long)s * 128 + lane * 4];
        acc.x += v.x; acc.y += v.y; acc.z += v.z; acc.w += v.w;
    }
    float inv = 1.0f / fmaxf((float)n, 1.0f);
    acc.x *= inv; acc.y *= inv; acc.z *= inv; acc.w *= inv;
    *(float4*)&mean[(long)w * 128 + lane * 4] = acc;
}

// ---------------- fused SAGE GEMM, 128x128 tile, packed f32x2 ---------------
// out[M,128] = mean @ Wl + h @ Wr + b  (K = 2 chunks of 128)
__device__ __forceinline__ unsigned long long dup2(float a) {
    unsigned long long r;
    asm("mov.b64 %0, {%1, %1};" : "=l"(r) : "f"(a));
    return r;
}
__device__ __forceinline__ void fma2(unsigned long long& d,
                                     unsigned long long a, unsigned long long b) {
    asm("fma.rn.f32x2 %0, %1, %2, %0;" : "+l"(d) : "l"(a), "l"(b));
}

__global__ void __launch_bounds__(256, 1)
k_gemm(const float* __restrict__ Mean, const float* __restrict__ H,
       const float* __restrict__ Wl, const float* __restrict__ Wr,
       const float* __restrict__ bias, float* __restrict__ out, int do_relu) {
    extern __shared__ float smem[];
    float* Ws = smem;              // [128][128] 64 KB
    float* As = smem + 128 * 128;  // [128][128] 64 KB (row-major rows of A)

    int tid  = threadIdx.x;
    int tc   = tid & 15;   // col group: cols [8*tc, 8*tc+7]
    int tr   = tid >> 4;   // row group: rows [8*tr, 8*tr+7]
    int row0 = blockIdx.x * 128;

    unsigned long long acc[8][4];
#pragma unroll
    for (int i = 0; i < 8; i++)
#pragma unroll
        for (int j = 0; j < 4; j++) acc[i][j] = 0ull;

    const float4 zero4 = make_float4(0.f, 0.f, 0.f, 0.f);

#pragma unroll
    for (int c = 0; c < 2; c++) {
        const float* Asrc = c ? H  : Mean;
        const float* Wsrc = c ? Wr : Wl;
        if (c) __syncthreads();
        // stage W chunk (direct copy, [k][n] row-major)
#pragma unroll
        for (int i = tid; i < 4096; i += 256)
            ((float4*)Ws)[i] = ((const float4*)Wsrc)[i];
        // stage A chunk rows [row0, row0+128) (coalesced)
#pragma unroll
        for (int i = tid; i < 4096; i += 256) {
            int r  = i >> 5;
            int v  = i & 31;
            int gr = row0 + r;
            ((float4*)As)[i] = (gr < NN)
                ? ((const float4*)&Asrc[(long)gr * 128])[v] : zero4;
        }
        __syncthreads();

#pragma unroll 2
        for (int k = 0; k < 128; ++k) {
            float4 w0 = *(const float4*)&Ws[k * 128 + tc * 8];
            float4 w1 = *(const float4*)&Ws[k * 128 + tc * 8 + 4];
            unsigned long long b2[4];
            b2[0] = ((const unsigned long long*)&w0)[0];
            b2[1] = ((const unsigned long long*)&w0)[1];
            b2[2] = ((const unsigned long long*)&w1)[0];
            b2[3] = ((const unsigned long long*)&w1)[1];
#pragma unroll
            for (int i = 0; i < 8; i++) {
                unsigned long long a2 = dup2(As[(tr * 8 + i) * 128 + k]);
                fma2(acc[i][0], a2, b2[0]);
                fma2(acc[i][1], a2, b2[1]);
                fma2(acc[i][2], a2, b2[2]);
                fma2(acc[i][3], a2, b2[3]);
            }
        }
    }

    // epilogue
    float bv[8];
#pragma unroll
    for (int j = 0; j < 8; j++) bv[j] = bias[tc * 8 + j];
#pragma unroll
    for (int i = 0; i < 8; i++) {
        int gr = row0 + tr * 8 + i;
        if (gr >= NN) continue;
        float o[8];
#pragma unroll
        for (int j = 0; j < 4; j++) {
            unsigned int lo, hi;
            asm("mov.b64 {%0, %1}, %2;" : "=r"(lo), "=r"(hi) : "l"(acc[i][j]));
            o[2 * j]     = __uint_as_float(lo) + bv[2 * j];
            o[2 * j + 1] = __uint_as_float(hi) + bv[2 * j + 1];
        }
        if (do_relu) {
#pragma unroll
            for (int j = 0; j < 8; j++) o[j] = fmaxf(o[j], 0.0f);
        }
        float4 s0 = make_float4(o[0], o[1], o[2], o[3]);
        float4 s1 = make_float4(o[4], o[5], o[6], o[7]);
        *(float4*)&out[(long)gr * 128 + tc * 8]     = s0;
        *(float4*)&out[(long)gr * 128 + tc * 8 + 4] = s1;
    }
}

// ---------------- edge-wise dot product ------------------------------------
__global__ void k_edgedot(const float* __restrict__ h2,
                          const int* __restrict__ eli,
                          float* __restrict__ out) {
    int w    = (blockIdx.x * blockDim.x + threadIdx.x) >> 5;
    int lane = threadIdx.x & 31;
    if (w >= NL) return;
    int s = eli[w];
    int d = eli[NL + w];
    float4 a = *(const float4*)&h2[(long)s * 128 + lane * 4];
    float4 b = *(const float4*)&h2[(long)d * 128 + lane * 4];
    float sum = a.x * b.x + a.y * b.y + a.z * b.z + a.w * b.w;
#pragma unroll
    for (int o = 16; o; o >>= 1) sum += __shfl_xor_sync(0xffffffffu, sum, o);
    if (lane == 0) out[w] = sum;
}

// ---------------- launch ----------------------------------------------------
extern "C" void kernel_launch(void* const* d_in, const int* in_sizes, int n_in,
                              void* d_out, int out_size) {
    const int*   n_id = (const int*)d_in[0];
    const float* x    = (const float*)d_in[1];
    const int*   ei   = (const int*)d_in[2];   // [2, NE]
    const int*   eli  = (const int*)d_in[3];   // [2, NL]
    const float* emb  = (const float*)d_in[4];
    const float* W1l  = (const float*)d_in[5];
    const float* W1r  = (const float*)d_in[6];
    const float* b1   = (const float*)d_in[7];
    const float* W2l  = (const float*)d_in[8];
    const float* W2r  = (const float*)d_in[9];
    const float* b2   = (const float*)d_in[10];
    float* out = (float*)d_out;

    float *h0, *mean, *h1, *h2;
    int *deg, *rowptr, *cursor, *col, *bsums;
    cudaGetSymbolAddress((void**)&h0,     g_h0);
    cudaGetSymbolAddress((void**)&mean,   g_mean);
    cudaGetSymbolAddress((void**)&h1,     g_h1);
    cudaGetSymbolAddress((void**)&h2,     g_h2);
    cudaGetSymbolAddress((void**)&deg,    g_deg);
    cudaGetSymbolAddress((void**)&rowptr, g_rowptr);
    cudaGetSymbolAddress((void**)&cursor, g_cursor);
    cudaGetSymbolAddress((void**)&col,    g_col);
    cudaGetSymbolAddress((void**)&bsums,  g_bsums);

    const int SMEM = 2 * 128 * 128 * 4;  // 128 KB
    cudaFuncSetAttribute(k_gemm, cudaFuncAttributeMaxDynamicSharedMemorySize, SMEM);

    const int NB_SCAN = (NN + 1023) / 1024;  // 49

    cudaMemsetAsync(deg,    0, sizeof(int) * NN);
    cudaMemsetAsync(cursor, 0, sizeof(int) * NN);

    k_concat<<<(NN * 32 + 255) / 256, 256>>>(n_id, x, emb, h0);

    // CSR build (dst-indexed, col = src)
    k_deg<<<(NE + 255) / 256, 256>>>(ei + NE, deg);
    k_scan1<<<NB_SCAN, 1024>>>(deg, rowptr, bsums);
    k_scan2<<<1, 32>>>(bsums, NB_SCAN);
    k_scan3<<<NB_SCAN, 1024>>>(rowptr, bsums);
    k_fill<<<(NE + 255) / 256, 256>>>(ei, ei + NE, rowptr, cursor, col);

    // layer 1
    k_agg<<<(NN * 32 + 255) / 256, 256>>>(h0, rowptr, deg, col, mean);
    k_gemm<<<(NN + 127) / 128, 256, SMEM>>>(mean, h0, W1l, W1r, b1, h1, 1);

    // layer 2
    k_agg<<<(NN * 32 + 255) / 256, 256>>>(h1, rowptr, deg, col, mean);
    k_gemm<<<(NN + 127) / 128, 256, SMEM>>>(mean, h1, W2l, W2r, b2, h2, 0);

    // classifier
    k_edgedot<<<(NL * 32 + 255) / 256, 256>>>(h2, eli, out);
}

// round 4
// speedup vs baseline: 3.7714x; 1.3967x over previous
#include <cuda_runtime.h>
#include <cuda_bf16.h>
#include <cstdint>

#define NN 50000
#define D  128
#define NE 800000
#define NL 200000

// ---------------- scratch ----------------------------------------------------
__device__ float g_h0[NN * D];
__device__ float g_mean[NN * D];
__device__ float g_h1[NN * D];
__device__ float g_h2[NN * D];
__device__ int   g_deg[NN];
__device__ int   g_rowptr[NN];
__device__ int   g_cursor[NN];
__device__ int   g_col[NE];
__device__ int   g_bsums[64];
// B fragments: [layer(2)][kstep(16)][ntile(16)][lane(32)] x uint4{b0h,b1h,b0l,b1l}
__device__ uint4 g_bfrag[2 * 16 * 16 * 32];

// ---------------- bf16 split helpers -----------------------------------------
__device__ __forceinline__ void split2(float x0, float x1,
                                       uint32_t& hp, uint32_t& lp) {
    __nv_bfloat16 h0 = __float2bfloat16_rn(x0);
    __nv_bfloat16 h1 = __float2bfloat16_rn(x1);
    float r0 = x0 - __bfloat162float(h0);
    float r1 = x1 - __bfloat162float(h1);
    __nv_bfloat16 l0 = __float2bfloat16_rn(r0);
    __nv_bfloat16 l1 = __float2bfloat16_rn(r1);
    hp = ((uint32_t)__bfloat16_as_ushort(h1) << 16) | __bfloat16_as_ushort(h0);
    lp = ((uint32_t)__bfloat16_as_ushort(l1) << 16) | __bfloat16_as_ushort(l0);
}

__device__ __forceinline__ uint32_t su32(const void* p) {
    uint32_t a;
    asm("{ .reg .u64 t; cvta.to.shared.u64 t, %1; cvt.u32.u64 %0, t; }"
        : "=r"(a) : "l"(p));
    return a;
}

#define LDSM4(r, addr) \
    asm volatile("ldmatrix.sync.aligned.m8n8.x4.shared.b16 {%0,%1,%2,%3}, [%4];" \
                 : "=r"((r)[0]), "=r"((r)[1]), "=r"((r)[2]), "=r"((r)[3]) : "r"(addr))

#define MMA_BF16(d, a, b) \
    asm volatile("mma.sync.aligned.m16n8k16.row.col.f32.bf16.bf16.f32 " \
                 "{%0,%1,%2,%3},{%4,%5,%6,%7},{%8,%9},{%0,%1,%2,%3};" \
                 : "+f"((d)[0]), "+f"((d)[1]), "+f"((d)[2]), "+f"((d)[3]) \
                 : "r"((a)[0]), "r"((a)[1]), "r"((a)[2]), "r"((a)[3]), \
                   "r"((b)[0]), "r"((b)[1]))

// ---------------- h0 = concat(emb[n_id], x_struct) --------------------------
__global__ void k_concat(const int* __restrict__ n_id,
                         const float* __restrict__ x,
                         const float* __restrict__ emb,
                         float* __restrict__ h0) {
    int t = blockIdx.x * blockDim.x + threadIdx.x;
    if (t >= NN * 32) return;
    int i = t >> 5;
    int q = t & 31;
    float4 v;
    if (q < 16) v = *(const float4*)&emb[(long)n_id[i] * 64 + q * 4];
    else        v = *(const float4*)&x[(long)i * 64 + (q - 16) * 4];
    *(float4*)&h0[(long)i * 128 + q * 4] = v;
}

// ---------------- W -> per-lane bf16 B-fragment precompute -------------------
// mma m16n8k16 B fragment (col-major k16 x n8): gid=lane>>2, tig=lane&3.
//   b0 elements e=0,1: k = 2*tig+e,      n = gid
//   b1 elements e=0,1: k = 2*tig+e + 8,  n = gid
__global__ void k_wsplit(const float* __restrict__ W1l, const float* __restrict__ W1r,
                         const float* __restrict__ W2l, const float* __restrict__ W2r,
                         uint4* __restrict__ bf) {
    int t = blockIdx.x * blockDim.x + threadIdx.x;
    if (t >= 2 * 16 * 16 * 32) return;
    int L    = t >> 13;
    int s    = (t >> 9) & 15;   // kstep (k0 = 16*s over K=256)
    int n    = (t >> 5) & 15;   // ntile
    int lane = t & 31;
    int gid = lane >> 2, tig = lane & 3;
    int col = n * 8 + gid;
    const float* Wl = L ? W2l : W1l;
    const float* Wr = L ? W2r : W1r;

    uint32_t bh[2], bl[2];
#pragma unroll
    for (int r = 0; r < 2; r++) {
        float v0, v1;
        int k0 = s * 16 + r * 8 + 2 * tig;
        v0 = (k0     < 128) ? Wl[k0 * 128 + col]       : Wr[(k0 - 128) * 128 + col];
        v1 = (k0 + 1 < 128) ? Wl[(k0 + 1) * 128 + col] : Wr[(k0 + 1 - 128) * 128 + col];
        split2(v0, v1, bh[r], bl[r]);
    }
    bf[t] = make_uint4(bh[0], bh[1], bl[0], bl[1]);
}

// ---------------- CSR build ---------------------------------------------------
__global__ void k_deg(const int* __restrict__ dst, int* __restrict__ deg) {
    int e = blockIdx.x * blockDim.x + threadIdx.x;
    if (e < NE) atomicAdd(&deg[dst[e]], 1);
}

__global__ void k_scan1(const int* __restrict__ deg, int* __restrict__ out,
                        int* __restrict__ bsums) {
    __shared__ int sh[1024];
    int gid = blockIdx.x * 1024 + threadIdx.x;
    int v = (gid < NN) ? deg[gid] : 0;
    sh[threadIdx.x] = v;
    __syncthreads();
#pragma unroll
    for (int off = 1; off < 1024; off <<= 1) {
        int t = (threadIdx.x >= off) ? sh[threadIdx.x - off] : 0;
        __syncthreads();
        sh[threadIdx.x] += t;
        __syncthreads();
    }
    if (gid < NN) out[gid] = sh[threadIdx.x] - v;
    if (threadIdx.x == 1023) bsums[blockIdx.x] = sh[1023];
}

__global__ void k_scan2(int* __restrict__ bsums, int nb) {
    if (threadIdx.x == 0) {
        int acc = 0;
        for (int i = 0; i < nb; i++) { int t = bsums[i]; bsums[i] = acc; acc += t; }
    }
}

__global__ void k_scan3(int* __restrict__ out, const int* __restrict__ bsums) {
    int gid = blockIdx.x * 1024 + threadIdx.x;
    if (gid < NN) out[gid] += bsums[blockIdx.x];
}

__global__ void k_fill(const int* __restrict__ src, const int* __restrict__ dst,
                       const int* __restrict__ rowptr, int* __restrict__ cursor,
                       int* __restrict__ col) {
    int e = blockIdx.x * blockDim.x + threadIdx.x;
    if (e >= NE) return;
    int d = dst[e];
    int pos = rowptr[d] + atomicAdd(&cursor[d], 1);
    col[pos] = src[e];
}

// ---------------- mean aggregation (warp per node) ---------------------------
__global__ void k_agg(const float* __restrict__ h,
                      const int* __restrict__ rowptr,
                      const int* __restrict__ deg,
                      const int* __restrict__ col,
                      float* __restrict__ mean) {
    int w    = (blockIdx.x * blockDim.x + threadIdx.x) >> 5;
    int lane = threadIdx.x & 31;
    if (w >= NN) return;
    int start = rowptr[w];
    int n     = deg[w];
    float4 acc = make_float4(0.f, 0.f, 0.f, 0.f);
    int j = 0;
    for (; j + 4 <= n; j += 4) {
        int s0 = col[start + j];
        int s1 = col[start + j + 1];
        int s2 = col[start + j + 2];
        int s3 = col[start + j + 3];
        float4 v0 = *(const float4*)&h[(long)s0 * 128 + lane * 4];
        float4 v1 = *(const float4*)&h[(long)s1 * 128 + lane * 4];
        float4 v2 = *(const float4*)&h[(long)s2 * 128 + lane * 4];
        float4 v3 = *(const float4*)&h[(long)s3 * 128 + lane * 4];
        acc.x += v0.x + v1.x + v2.x + v3.x;
        acc.y += v0.y + v1.y + v2.y + v3.y;
        acc.z += v0.z + v1.z + v2.z + v3.z;
        acc.w += v0.w + v1.w + v2.w + v3.w;
    }
    for (; j < n; j++) {
        int s = col[start + j];
        float4 v = *(const float4*)&h[(long)s * 128 + lane * 4];
        acc.x += v.x; acc.y += v.y; acc.z += v.z; acc.w += v.w;
    }
    float inv = 1.0f / fmaxf((float)n, 1.0f);
    acc.x *= inv; acc.y *= inv; acc.z *= inv; acc.w *= inv;
    *(float4*)&mean[(long)w * 128 + lane * 4] = acc;
}

// ---------------- mma.sync bf16 2-split GEMM ---------------------------------
// out[M,128] = [mean|h](K=256) @ [Wl;Wr] + b
// Block: 256 thr, 128 rows. Warp (wm=w&3, wn=w>>2): rows wm*32..+31, cols wn*64..+63.
// A staged per 32-k chunk to smem (bf16 hi/lo planes, pitch 40 halfwords),
// double-buffered. B fragments streamed from g_bfrag via LDG.128.
#define APITCH 40           // halfwords per row
#define PLANE  (128 * APITCH * 2)   // 10240 bytes

__global__ void __launch_bounds__(256, 1)
k_gemm_mma(const float* __restrict__ Mean, const float* __restrict__ H,
           const uint4* __restrict__ Bf, const float* __restrict__ bias,
           float* __restrict__ out, int do_relu) {
    __shared__ __align__(16) uint8_t sA[2][2][PLANE];  // [buf][hi/lo]

    int tid  = threadIdx.x;
    int wid  = tid >> 5;
    int lane = tid & 31;
    int wm   = wid & 3;
    int wn   = wid >> 2;
    int gid  = lane >> 2, tig = lane & 3;
    int row0 = blockIdx.x * 128;

    int laneRow = lane & 15;
    int laneKo  = (lane >> 4) * 8;

    uint32_t sbase = su32(&sA[0][0][0]);

    float acc[2][8][4];
#pragma unroll
    for (int mt = 0; mt < 2; mt++)
#pragma unroll
        for (int nt = 0; nt < 8; nt++)
#pragma unroll
            for (int j = 0; j < 4; j++) acc[mt][nt][j] = 0.f;

    const float4 z4 = make_float4(0.f, 0.f, 0.f, 0.f);

    // ---- stage chunk 0 ----
    {
        const float* Asrc = Mean;
#pragma unroll
        for (int i = 0; i < 2; i++) {
            int t   = tid + 256 * i;
            int row = t >> 2, q = t & 3;
            int gr  = row0 + row;
            float4 a = (gr < NN) ? *(const float4*)&Asrc[(long)gr * 128 + q * 8]     : z4;
            float4 b = (gr < NN) ? *(const float4*)&Asrc[(long)gr * 128 + q * 8 + 4] : z4;
            uint4 hv, lv;
            split2(a.x, a.y, hv.x, lv.x);
            split2(a.z, a.w, hv.y, lv.y);
            split2(b.x, b.y, hv.z, lv.z);
            split2(b.z, b.w, hv.w, lv.w);
            int off = row * (APITCH * 2) + q * 16;
            *(uint4*)&sA[0][0][off] = hv;
            *(uint4*)&sA[0][1][off] = lv;
        }
    }

#pragma unroll 1
    for (int c = 0; c < 8; ++c) {
        __syncthreads();

        // prefetch next chunk from global
        float4 rg[4];
        if (c < 7) {
            const float* Asrc = (c + 1 < 4) ? Mean : H;
            int bk = ((c + 1) & 3) * 32;
#pragma unroll
            for (int i = 0; i < 2; i++) {
                int t   = tid + 256 * i;
                int row = t >> 2, q = t & 3;
                int gr  = row0 + row;
                rg[2 * i]     = (gr < NN) ? *(const float4*)&Asrc[(long)gr * 128 + bk + q * 8]     : z4;
                rg[2 * i + 1] = (gr < NN) ? *(const float4*)&Asrc[(long)gr * 128 + bk + q * 8 + 4] : z4;
            }
        }

        // mma over buffer c&1
        uint32_t aBase = sbase + (uint32_t)((c & 1) * 2 * PLANE);
#pragma unroll
        for (int ks = 0; ks < 2; ks++) {
            int s = c * 2 + ks;
            uint32_t ah[2][4], al[2][4];
#pragma unroll
            for (int mt = 0; mt < 2; mt++) {
                uint32_t addr = aBase
                    + (uint32_t)((wm * 32 + mt * 16 + laneRow) * (APITCH * 2)
                                 + (ks * 16 + laneKo) * 2);
                LDSM4(ah[mt], addr);
                LDSM4(al[mt], addr + PLANE);
            }
            uint4 bf[8];
#pragma unroll
            for (int nt = 0; nt < 8; nt++)
                bf[nt] = __ldg(&Bf[(s * 16 + wn * 8 + nt) * 32 + lane]);
#pragma unroll
            for (int nt = 0; nt < 8; nt++) {
                uint32_t bh[2] = {bf[nt].x, bf[nt].y};
                uint32_t bl[2] = {bf[nt].z, bf[nt].w};
#pragma unroll
                for (int mt = 0; mt < 2; mt++) {
                    MMA_BF16(acc[mt][nt], ah[mt], bh);
                    MMA_BF16(acc[mt][nt], ah[mt], bl);
                    MMA_BF16(acc[mt][nt], al[mt], bh);
                }
            }
        }

        // store prefetched chunk into other buffer
        if (c < 7) {
            int nb = (c + 1) & 1;
#pragma unroll
            for (int i = 0; i < 2; i++) {
                int t   = tid + 256 * i;
                int row = t >> 2, q = t & 3;
                uint4 hv, lv;
                float4 a = rg[2 * i], b = rg[2 * i + 1];
                split2(a.x, a.y, hv.x, lv.x);
                split2(a.z, a.w, hv.y, lv.y);
                split2(b.x, b.y, hv.z, lv.z);
                split2(b.z, b.w, hv.w, lv.w);
                int off = row * (APITCH * 2) + q * 16;
                *(uint4*)&sA[nb][0][off] = hv;
                *(uint4*)&sA[nb][1][off] = lv;
            }
        }
    }

    // ---- epilogue ----
#pragma unroll
    for (int mt = 0; mt < 2; mt++) {
        int r0 = row0 + wm * 32 + mt * 16 + gid;
        int r1 = r0 + 8;
#pragma unroll
        for (int nt = 0; nt < 8; nt++) {
            int cbase = wn * 64 + nt * 8 + tig * 2;
            float bx = __ldg(&bias[cbase]);
            float by = __ldg(&bias[cbase + 1]);
            float2 v0 = make_float2(acc[mt][nt][0] + bx, acc[mt][nt][1] + by);
            float2 v1 = make_float2(acc[mt][nt][2] + bx, acc[mt][nt][3] + by);
            if (do_relu) {
                v0.x = fmaxf(v0.x, 0.f); v0.y = fmaxf(v0.y, 0.f);
                v1.x = fmaxf(v1.x, 0.f); v1.y = fmaxf(v1.y, 0.f);
            }
            if (r0 < NN) *(float2*)&out[(long)r0 * 128 + cbase] = v0;
            if (r1 < NN) *(float2*)&out[(long)r1 * 128 + cbase] = v1;
        }
    }
}

// ---------------- edge-wise dot product --------------------------------------
__global__ void k_edgedot(const float* __restrict__ h2,
                          const int* __restrict__ eli,
                          float* __restrict__ out) {
    int w    = (blockIdx.x * blockDim.x + threadIdx.x) >> 5;
    int lane = threadIdx.x & 31;
    if (w >= NL) return;
    int s = eli[w];
    int d = eli[NL + w];
    float4 a = *(const float4*)&h2[(long)s * 128 + lane * 4];
    float4 b = *(const float4*)&h2[(long)d * 128 + lane * 4];
    float sum = a.x * b.x + a.y * b.y + a.z * b.z + a.w * b.w;
#pragma unroll
    for (int o = 16; o; o >>= 1) sum += __shfl_xor_sync(0xffffffffu, sum, o);
    if (lane == 0) out[w] = sum;
}

// ---------------- launch ------------------------------------------------------
extern "C" void kernel_launch(void* const* d_in, const int* in_sizes, int n_in,
                              void* d_out, int out_size) {
    const int*   n_id = (const int*)d_in[0];
    const float* x    = (const float*)d_in[1];
    const int*   ei   = (const int*)d_in[2];
    const int*   eli  = (const int*)d_in[3];
    const float* emb  = (const float*)d_in[4];
    const float* W1l  = (const float*)d_in[5];
    const float* W1r  = (const float*)d_in[6];
    const float* b1   = (const float*)d_in[7];
    const float* W2l  = (const float*)d_in[8];
    const float* W2r  = (const float*)d_in[9];
    const float* b2   = (const float*)d_in[10];
    float* out = (float*)d_out;

    float *h0, *mean, *h1, *h2;
    int *deg, *rowptr, *cursor, *col, *bsums;
    uint4* bfrag;
    cudaGetSymbolAddress((void**)&h0,     g_h0);
    cudaGetSymbolAddress((void**)&mean,   g_mean);
    cudaGetSymbolAddress((void**)&h1,     g_h1);
    cudaGetSymbolAddress((void**)&h2,     g_h2);
    cudaGetSymbolAddress((void**)&deg,    g_deg);
    cudaGetSymbolAddress((void**)&rowptr, g_rowptr);
    cudaGetSymbolAddress((void**)&cursor, g_cursor);
    cudaGetSymbolAddress((void**)&col,    g_col);
    cudaGetSymbolAddress((void**)&bsums,  g_bsums);
    cudaGetSymbolAddress((void**)&bfrag,  g_bfrag);

    const int NB_SCAN = (NN + 1023) / 1024;

    cudaMemsetAsync(deg,    0, sizeof(int) * NN);
    cudaMemsetAsync(cursor, 0, sizeof(int) * NN);

    k_concat<<<(NN * 32 + 255) / 256, 256>>>(n_id, x, emb, h0);
    k_wsplit<<<(2 * 16 * 16 * 32 + 255) / 256, 256>>>(W1l, W1r, W2l, W2r, bfrag);

    k_deg<<<(NE + 255) / 256, 256>>>(ei + NE, deg);
    k_scan1<<<NB_SCAN, 1024>>>(deg, rowptr, bsums);
    k_scan2<<<1, 32>>>(bsums, NB_SCAN);
    k_scan3<<<NB_SCAN, 1024>>>(rowptr, bsums);
    k_fill<<<(NE + 255) / 256, 256>>>(ei, ei + NE, rowptr, cursor, col);

    const int GB = (NN + 127) / 128;  // 391

    // layer 1
    k_agg<<<(NN * 32 + 255) / 256, 256>>>(h0, rowptr, deg, col, mean);
    k_gemm_mma<<<GB, 256>>>(mean, h0, bfrag, b1, h1, 1);

    // layer 2
    k_agg<<<(NN * 32 + 255) / 256, 256>>>(h1, rowptr, deg, col, mean);
    k_gemm_mma<<<GB, 256>>>(mean, h1, bfrag + 8192, b2, h2, 0);

    // classifier
    k_edgedot<<<(NL * 32 + 255) / 256, 256>>>(h2, eli, out);
}

// round 6
// speedup vs baseline: 3.9611x; 1.0503x over previous
#include <cuda_runtime.h>
#include <cuda_bf16.h>
#include <cuda_fp16.h>
#include <cstdint>

#define NN 50000
#define D  128
#define NE 800000
#define NL 200000

// ---------------- scratch ----------------------------------------------------
__device__ float  g_h0[NN * D];
__device__ float  g_mean[NN * D];
__device__ float  g_h1[NN * D];
__device__ __half g_h0h[NN * D];
__device__ __half g_h1h[NN * D];
__device__ __half g_h2h[NN * D];
__device__ int    g_deg[NN];
__device__ int    g_rowptr[NN];
__device__ int    g_cursor[NN];
__device__ int    g_col[NE];
__device__ int    g_bsums[64];
// B fragments: [layer(2)][kstep(16)][ntile(16)][lane(32)] x uint4{b0h,b1h,b0l,b1l}
__device__ uint4  g_bfrag[2 * 16 * 16 * 32];

// ---------------- helpers -----------------------------------------------------
__device__ __forceinline__ void split2(float x0, float x1,
                                       uint32_t& hp, uint32_t& lp) {
    __nv_bfloat16 h0 = __float2bfloat16_rn(x0);
    __nv_bfloat16 h1 = __float2bfloat16_rn(x1);
    float r0 = x0 - __bfloat162float(h0);
    float r1 = x1 - __bfloat162float(h1);
    __nv_bfloat16 l0 = __float2bfloat16_rn(r0);
    __nv_bfloat16 l1 = __float2bfloat16_rn(r1);
    hp = ((uint32_t)__bfloat16_as_ushort(h1) << 16) | __bfloat16_as_ushort(h0);
    lp = ((uint32_t)__bfloat16_as_ushort(l1) << 16) | __bfloat16_as_ushort(l0);
}

__device__ __forceinline__ uint32_t su32(const void* p) {
    uint32_t a;
    asm("{ .reg .u64 t; cvta.to.shared.u64 t, %1; cvt.u32.u64 %0, t; }"
        : "=r"(a) : "l"(p));
    return a;
}

#define LDSM4(r, addr) \
    asm volatile("ldmatrix.sync.aligned.m8n8.x4.shared.b16 {%0,%1,%2,%3}, [%4];" \
                 : "=r"((r)[0]), "=r"((r)[1]), "=r"((r)[2]), "=r"((r)[3]) : "r"(addr))

#define MMA_BF16(d, a, b) \
    asm volatile("mma.sync.aligned.m16n8k16.row.col.f32.bf16.bf16.f32 " \
                 "{%0,%1,%2,%3},{%4,%5,%6,%7},{%8,%9},{%0,%1,%2,%3};" \
                 : "+f"((d)[0]), "+f"((d)[1]), "+f"((d)[2]), "+f"((d)[3]) \
                 : "r"((a)[0]), "r"((a)[1]), "r"((a)[2]), "r"((a)[3]), \
                   "r"((b)[0]), "r"((b)[1]))

// ---------------- fused prologue: concat + degree + wsplit -------------------
#define CB 6250   // concat blocks: NN*32/256
#define DB 3125   // degree blocks: NE/256
#define WB 64     // wsplit blocks: 16384/256

__global__ void k_pre(const int* __restrict__ n_id,
                      const float* __restrict__ x,
                      const float* __restrict__ emb,
                      const int* __restrict__ dst,
                      const float* __restrict__ W1l, const float* __restrict__ W1r,
                      const float* __restrict__ W2l, const float* __restrict__ W2r,
                      float* __restrict__ h0, __half* __restrict__ h0h,
                      int* __restrict__ deg, uint4* __restrict__ bf) {
    int b = blockIdx.x;
    if (b < CB) {
        int t = b * 256 + threadIdx.x;
        int i = t >> 5;
        int q = t & 31;
        float4 v;
        if (q < 16) v = *(const float4*)&emb[(long)n_id[i] * 64 + q * 4];
        else        v = *(const float4*)&x[(long)i * 64 + (q - 16) * 4];
        *(float4*)&h0[(long)i * 128 + q * 4] = v;
        __half2 p0 = __floats2half2_rn(v.x, v.y);
        __half2 p1 = __floats2half2_rn(v.z, v.w);
        *(__half2*)&h0h[(long)i * 128 + q * 4]     = p0;
        *(__half2*)&h0h[(long)i * 128 + q * 4 + 2] = p1;
    } else if (b < CB + DB) {
        int e = (b - CB) * 256 + threadIdx.x;
        if (e < NE) atomicAdd(&deg[dst[e]], 1);
    } else {
        int t = (b - CB - DB) * 256 + threadIdx.x;
        if (t < 2 * 16 * 16 * 32) {
            int L    = t >> 13;
            int s    = (t >> 9) & 15;
            int n    = (t >> 5) & 15;
            int lane = t & 31;
            int gid = lane >> 2, tig = lane & 3;
            int col = n * 8 + gid;
            const float* Wl = L ? W2l : W1l;
            const float* Wr = L ? W2r : W1r;
            uint32_t bh[2], bl[2];
#pragma unroll
            for (int r = 0; r < 2; r++) {
                int k0 = s * 16 + r * 8 + 2 * tig;
                float v0 = (k0     < 128) ? Wl[k0 * 128 + col]       : Wr[(k0 - 128) * 128 + col];
                float v1 = (k0 + 1 < 128) ? Wl[(k0 + 1) * 128 + col] : Wr[(k0 + 1 - 128) * 128 + col];
                split2(v0, v1, bh[r], bl[r]);
            }
            bf[t] = make_uint4(bh[0], bh[1], bl[0], bl[1]);
        }
    }
}

// ---------------- CSR build ---------------------------------------------------
__global__ void k_scan1(const int* __restrict__ deg, int* __restrict__ out,
                        int* __restrict__ bsums, int* __restrict__ cursor) {
    __shared__ int sh[1024];
    int gid = blockIdx.x * 1024 + threadIdx.x;
    int v = (gid < NN) ? deg[gid] : 0;
    sh[threadIdx.x] = v;
    __syncthreads();
#pragma unroll
    for (int off = 1; off < 1024; off <<= 1) {
        int t = (threadIdx.x >= off) ? sh[threadIdx.x - off] : 0;
        __syncthreads();
        sh[threadIdx.x] += t;
        __syncthreads();
    }
    if (gid < NN) {
        out[gid]    = sh[threadIdx.x] - v;
        cursor[gid] = 0;
    }
    if (threadIdx.x == 1023) bsums[blockIdx.x] = sh[1023];
}

// fused scan2+scan3: every block recomputes the 64-wide block-sum prefix
__global__ void k_scan3f(int* __restrict__ out, const int* __restrict__ bsums, int nb) {
    __shared__ int sh[64];
    int t = threadIdx.x;
    if (t < 32) {
        // inclusive scan of up to 64 block sums using one warp (2 elems/lane)
        int v0 = (t      < nb) ? bsums[t]      : 0;
        int v1 = (t + 32 < nb) ? bsums[t + 32] : 0;
#pragma unroll
        for (int off = 1; off < 32; off <<= 1) {
            int u0 = __shfl_up_sync(0xffffffffu, v0, off);
            int u1 = __shfl_up_sync(0xffffffffu, v1, off);
            if ((int)(t) >= off) { v0 += u0; v1 += u1; }
        }
        int tot0 = __shfl_sync(0xffffffffu, v0, 31);
        sh[t]      = v0;
        sh[t + 32] = v1 + tot0;
    }
    __syncthreads();
    int offv = (blockIdx.x == 0) ? 0 : sh[blockIdx.x - 1];
    int gid = blockIdx.x * 1024 + t;
    if (gid < NN) out[gid] += offv;
}

__global__ void k_fill(const int* __restrict__ src, const int* __restrict__ dst,
                       const int* __restrict__ rowptr, int* __restrict__ cursor,
                       int* __restrict__ col) {
    int e = blockIdx.x * blockDim.x + threadIdx.x;
    if (e >= NE) return;
    int d = dst[e];
    int pos = rowptr[d] + atomicAdd(&cursor[d], 1);
    col[pos] = src[e];
}

// ---------------- mean aggregation (warp per node, fp16 gather) --------------
__global__ void k_agg(const __half* __restrict__ h16,
                      const int* __restrict__ rowptr,
                      const int* __restrict__ deg,
                      const int* __restrict__ col,
                      float* __restrict__ mean) {
    int w    = (blockIdx.x * blockDim.x + threadIdx.x) >> 5;
    int lane = threadIdx.x & 31;
    if (w >= NN) return;
    int start = rowptr[w];
    int n     = deg[w];
    float4 acc = make_float4(0.f, 0.f, 0.f, 0.f);
    const uint2* hp = (const uint2*)h16;   // 4 halves per uint2
    int j = 0;
    for (; j + 4 <= n; j += 4) {
        int s0 = col[start + j];
        int s1 = col[start + j + 1];
        int s2 = col[start + j + 2];
        int s3 = col[start + j + 3];
        uint2 r0 = hp[(long)s0 * 32 + lane];
        uint2 r1 = hp[(long)s1 * 32 + lane];
        uint2 r2 = hp[(long)s2 * 32 + lane];
        uint2 r3 = hp[(long)s3 * 32 + lane];
#pragma unroll
        for (int u = 0; u < 4; u++) {
            uint2 raw = (u == 0) ? r0 : (u == 1) ? r1 : (u == 2) ? r2 : r3;
            float2 a = __half22float2(*(const __half2*)&raw.x);
            float2 b = __half22float2(*(const __half2*)&raw.y);
            acc.x += a.x; acc.y += a.y; acc.z += b.x; acc.w += b.y;
        }
    }
    for (; j < n; j++) {
        int s = col[start + j];
        uint2 raw = hp[(long)s * 32 + lane];
        float2 a = __half22float2(*(const __half2*)&raw.x);
        float2 b = __half22float2(*(const __half2*)&raw.y);
        acc.x += a.x; acc.y += a.y; acc.z += b.x; acc.w += b.y;
    }
    float inv = 1.0f / fmaxf((float)n, 1.0f);
    acc.x *= inv; acc.y *= inv; acc.z *= inv; acc.w *= inv;
    *(float4*)&mean[(long)w * 128 + lane * 4] = acc;
}

// ---------------- mma.sync bf16 2-split GEMM ---------------------------------
#define APITCH 40
#define PLANE  (128 * APITCH * 2)

__global__ void __launch_bounds__(256, 1)
k_gemm_mma(const float* __restrict__ Mean, const float* __restrict__ H,
           const uint4* __restrict__ Bf, const float* __restrict__ bias,
           float* __restrict__ outf, __half* __restrict__ outh, int do_relu) {
    __shared__ __align__(16) uint8_t sA[2][2][PLANE];

    int tid  = threadIdx.x;
    int wid  = tid >> 5;
    int lane = tid & 31;
    int wm   = wid & 3;
    int wn   = wid >> 2;
    int gid  = lane >> 2, tig = lane & 3;
    int row0 = blockIdx.x * 128;

    int laneRow = lane & 15;
    int laneKo  = (lane >> 4) * 8;

    uint32_t sbase = su32(&sA[0][0][0]);

    float acc[2][8][4];
#pragma unroll
    for (int mt = 0; mt < 2; mt++)
#pragma unroll
        for (int nt = 0; nt < 8; nt++)
#pragma unroll
            for (int j = 0; j < 4; j++) acc[mt][nt][j] = 0.f;

    const float4 z4 = make_float4(0.f, 0.f, 0.f, 0.f);

    {
        const float* Asrc = Mean;
#pragma unroll
        for (int i = 0; i < 2; i++) {
            int t   = tid + 256 * i;
            int row = t >> 2, q = t & 3;
            int gr  = row0 + row;
            float4 a = (gr < NN) ? *(const float4*)&Asrc[(long)gr * 128 + q * 8]     : z4;
            float4 b = (gr < NN) ? *(const float4*)&Asrc[(long)gr * 128 + q * 8 + 4] : z4;
            uint4 hv, lv;
            split2(a.x, a.y, hv.x, lv.x);
            split2(a.z, a.w, hv.y, lv.y);
            split2(b.x, b.y, hv.z, lv.z);
            split2(b.z, b.w, hv.w, lv.w);
            int off = row * (APITCH * 2) + q * 16;
            *(uint4*)&sA[0][0][off] = hv;
            *(uint4*)&sA[0][1][off] = lv;
        }
    }

#pragma unroll 1
    for (int c = 0; c < 8; ++c) {
        __syncthreads();

        float4 rg[4];
        if (c < 7) {
            const float* Asrc = (c + 1 < 4) ? Mean : H;
            int bk = ((c + 1) & 3) * 32;
#pragma unroll
            for (int i = 0; i < 2; i++) {
                int t   = tid + 256 * i;
                int row = t >> 2, q = t & 3;
                int gr  = row0 + row;
                rg[2 * i]     = (gr < NN) ? *(const float4*)&Asrc[(long)gr * 128 + bk + q * 8]     : z4;
                rg[2 * i + 1] = (gr < NN) ? *(const float4*)&Asrc[(long)gr * 128 + bk + q * 8 + 4] : z4;
            }
        }

        uint32_t aBase = sbase + (uint32_t)((c & 1) * 2 * PLANE);
#pragma unroll
        for (int ks = 0; ks < 2; ks++) {
            int s = c * 2 + ks;
            uint32_t ah[2][4], al[2][4];
#pragma unroll
            for (int mt = 0; mt < 2; mt++) {
                uint32_t addr = aBase
                    + (uint32_t)((wm * 32 + mt * 16 + laneRow) * (APITCH * 2)
                                 + (ks * 16 + laneKo) * 2);
                LDSM4(ah[mt], addr);
                LDSM4(al[mt], addr + PLANE);
            }
            uint4 bf[8];
#pragma unroll
            for (int nt = 0; nt < 8; nt++)
                bf[nt] = __ldg(&Bf[(s * 16 + wn * 8 + nt) * 32 + lane]);
#pragma unroll
            for (int nt = 0; nt < 8; nt++) {
                uint32_t bh[2] = {bf[nt].x, bf[nt].y};
                uint32_t bl[2] = {bf[nt].z, bf[nt].w};
#pragma unroll
                for (int mt = 0; mt < 2; mt++) {
                    MMA_BF16(acc[mt][nt], ah[mt], bh);
                    MMA_BF16(acc[mt][nt], ah[mt], bl);
                    MMA_BF16(acc[mt][nt], al[mt], bh);
                }
            }
        }

        if (c < 7) {
            int nb = (c + 1) & 1;
#pragma unroll
            for (int i = 0; i < 2; i++) {
                int t   = tid + 256 * i;
                int row = t >> 2, q = t & 3;
                uint4 hv, lv;
                float4 a = rg[2 * i], b = rg[2 * i + 1];
                split2(a.x, a.y, hv.x, lv.x);
                split2(a.z, a.w, hv.y, lv.y);
                split2(b.x, b.y, hv.z, lv.z);
                split2(b.z, b.w, hv.w, lv.w);
                int off = row * (APITCH * 2) + q * 16;
                *(uint4*)&sA[nb][0][off] = hv;
                *(uint4*)&sA[nb][1][off] = lv;
            }
        }
    }

    // ---- epilogue: fp32 (optional) + fp16 shadow ----
#pragma unroll
    for (int mt = 0; mt < 2; mt++) {
        int r0 = row0 + wm * 32 + mt * 16 + gid;
        int r1 = r0 + 8;
#pragma unroll
        for (int nt = 0; nt < 8; nt++) {
            int cbase = wn * 64 + nt * 8 + tig * 2;
            float bx = __ldg(&bias[cbase]);
            float by = __ldg(&bias[cbase + 1]);
            float2 v0 = make_float2(acc[mt][nt][0] + bx, acc[mt][nt][1] + by);
            float2 v1 = make_float2(acc[mt][nt][2] + bx, acc[mt][nt][3] + by);
            if (do_relu) {
                v0.x = fmaxf(v0.x, 0.f); v0.y = fmaxf(v0.y, 0.f);
                v1.x = fmaxf(v1.x, 0.f); v1.y = fmaxf(v1.y, 0.f);
            }
            if (r0 < NN) {
                if (outf) *(float2*)&outf[(long)r0 * 128 + cbase] = v0;
                *(__half2*)&outh[(long)r0 * 128 + cbase] = __floats2half2_rn(v0.x, v0.y);
            }
            if (r1 < NN) {
                if (outf) *(float2*)&outf[(long)r1 * 128 + cbase] = v1;
                *(__half2*)&outh[(long)r1 * 128 + cbase] = __floats2half2_rn(v1.x, v1.y);
            }
        }
    }
}

// ---------------- edge-wise dot product (fp16 gather) -------------------------
__global__ void k_edgedot(const __half* __restrict__ h16,
                          const int* __restrict__ eli,
                          float* __restrict__ out) {
    int w    = (blockIdx.x * blockDim.x + threadIdx.x) >> 5;
    int lane = threadIdx.x & 31;
    if (w >= NL) return;
    int s = eli[w];
    int d = eli[NL + w];
    const uint2* hp = (const uint2*)h16;
    uint2 ra = hp[(long)s * 32 + lane];
    uint2 rb = hp[(long)d * 32 + lane];
    float2 a0 = __half22float2(*(const __half2*)&ra.x);
    float2 a1 = __half22float2(*(const __half2*)&ra.y);
    float2 b0 = __half22float2(*(const __half2*)&rb.x);
    float2 b1 = __half22float2(*(const __half2*)&rb.y);
    float sum = a0.x * b0.x + a0.y * b0.y + a1.x * b1.x + a1.y * b1.y;
#pragma unroll
    for (int o = 16; o; o >>= 1) sum += __shfl_xor_sync(0xffffffffu, sum, o);
    if (lane == 0) out[w] = sum;
}

// ---------------- launch ------------------------------------------------------
extern "C" void kernel_launch(void* const* d_in, const int* in_sizes, int n_in,
                              void* d_out, int out_size) {
    const int*   n_id = (const int*)d_in[0];
    const float* x    = (const float*)d_in[1];
    const int*   ei   = (const int*)d_in[2];
    const int*   eli  = (const int*)d_in[3];
    const float* emb  = (const float*)d_in[4];
    const float* W1l  = (const float*)d_in[5];
    const float* W1r  = (const float*)d_in[6];
    const float* b1   = (const float*)d_in[7];
    const float* W2l  = (const float*)d_in[8];
    const float* W2r  = (const float*)d_in[9];
    const float* b2   = (const float*)d_in[10];
    float* out = (float*)d_out;

    float *h0, *mean, *h1;
    __half *h0h, *h1h, *h2h;
    int *deg, *rowptr, *cursor, *col, *bsums;
    uint4* bfrag;
    cudaGetSymbolAddress((void**)&h0,     g_h0);
    cudaGetSymbolAddress((void**)&mean,   g_mean);
    cudaGetSymbolAddress((void**)&h1,     g_h1);
    cudaGetSymbolAddress((void**)&h0h,    g_h0h);
    cudaGetSymbolAddress((void**)&h1h,    g_h1h);
    cudaGetSymbolAddress((void**)&h2h,    g_h2h);
    cudaGetSymbolAddress((void**)&deg,    g_deg);
    cudaGetSymbolAddress((void**)&rowptr, g_rowptr);
    cudaGetSymbolAddress((void**)&cursor, g_cursor);
    cudaGetSymbolAddress((void**)&col,    g_col);
    cudaGetSymbolAddress((void**)&bsums,  g_bsums);
    cudaGetSymbolAddress((void**)&bfrag,  g_bfrag);

    const int NB_SCAN = (NN + 1023) / 1024;  // 49

    cudaMemsetAsync(deg, 0, sizeof(int) * NN);

    // fused prologue: concat(+fp16 shadow) + degree + wsplit
    k_pre<<<CB + DB + WB, 256>>>(n_id, x, emb, ei + NE, W1l, W1r, W2l, W2r,
                                 h0, h0h, deg, bfrag);
    k_scan1<<<NB_SCAN, 1024>>>(deg, rowptr, bsums, cursor);
    k_scan3f<<<NB_SCAN, 1024>>>(rowptr, bsums, NB_SCAN);
    k_fill<<<(NE + 255) / 256, 256>>>(ei, ei + NE, rowptr, cursor, col);

    const int GB = (NN + 127) / 128;  // 391

    // layer 1
    k_agg<<<(NN * 32 + 255) / 256, 256>>>(h0h, rowptr, deg, col, mean);
    k_gemm_mma<<<GB, 256>>>(mean, h0, bfrag, b1, h1, h1h, 1);

    // layer 2
    k_agg<<<(NN * 32 + 255) / 256, 256>>>(h1h, rowptr, deg, col, mean);
    k_gemm_mma<<<GB, 256>>>(mean, h1, bfrag + 8192, b2, nullptr, h2h, 0);

    // classifier
    k_edgedot<<<(NL * 32 + 255) / 256, 256>>>(h2h, eli, out);
}

// round 7
// speedup vs baseline: 5.5558x; 1.4026x over previous
#include <cuda_runtime.h>
#include <cuda_fp16.h>
#include <cstdint>

#define NN 50000
#define D  128
#define NE 800000
#define NL 200000

// ---------------- scratch ----------------------------------------------------
__device__ __half g_h0h[NN * D];
__device__ __half g_mean16[NN * D];
__device__ __half g_h1h[NN * D];
__device__ __half g_h2h[NN * D];
__device__ int    g_deg[NN];
__device__ int    g_rowptr[NN];
__device__ int    g_cursor[NN];
__device__ int    g_col[NE];
__device__ int    g_bsums[64];
// B fragments (fp16): [layer(2)][kstep(16)][ntile(16)][lane(32)] x uint2{b0,b1}
__device__ uint2  g_bfrag[2 * 16 * 16 * 32];

// ---------------- helpers -----------------------------------------------------
__device__ __forceinline__ uint32_t su32(const void* p) {
    uint32_t a;
    asm("{ .reg .u64 t; cvta.to.shared.u64 t, %1; cvt.u32.u64 %0, t; }"
        : "=r"(a) : "l"(p));
    return a;
}

#define LDSM4(r, addr) \
    asm volatile("ldmatrix.sync.aligned.m8n8.x4.shared.b16 {%0,%1,%2,%3}, [%4];" \
                 : "=r"((r)[0]), "=r"((r)[1]), "=r"((r)[2]), "=r"((r)[3]) : "r"(addr))

#define MMA_F16(d, a, b) \
    asm volatile("mma.sync.aligned.m16n8k16.row.col.f32.f16.f16.f32 " \
                 "{%0,%1,%2,%3},{%4,%5,%6,%7},{%8,%9},{%0,%1,%2,%3};" \
                 : "+f"((d)[0]), "+f"((d)[1]), "+f"((d)[2]), "+f"((d)[3]) \
                 : "r"((a)[0]), "r"((a)[1]), "r"((a)[2]), "r"((a)[3]), \
                   "r"((b)[0]), "r"((b)[1]))

// ---------------- fused prologue: concat + degree + wfrag --------------------
#define CB 6250   // concat blocks: NN*32/256
#define DB 3125   // degree blocks: NE/256
#define WB 64     // wfrag blocks: 16384/256

__global__ void k_pre(const int* __restrict__ n_id,
                      const float* __restrict__ x,
                      const float* __restrict__ emb,
                      const int* __restrict__ dst,
                      const float* __restrict__ W1l, const float* __restrict__ W1r,
                      const float* __restrict__ W2l, const float* __restrict__ W2r,
                      __half* __restrict__ h0h,
                      int* __restrict__ deg, uint2* __restrict__ bf) {
    int b = blockIdx.x;
    if (b < CB) {
        int t = b * 256 + threadIdx.x;
        int i = t >> 5;
        int q = t & 31;
        float4 v;
        if (q < 16) v = *(const float4*)&emb[(long)n_id[i] * 64 + q * 4];
        else        v = *(const float4*)&x[(long)i * 64 + (q - 16) * 4];
        __half2 p0 = __floats2half2_rn(v.x, v.y);
        __half2 p1 = __floats2half2_rn(v.z, v.w);
        uint2 pk = make_uint2(*(uint32_t*)&p0, *(uint32_t*)&p1);
        *(uint2*)&h0h[(long)i * 128 + q * 4] = pk;
    } else if (b < CB + DB) {
        int e = (b - CB) * 256 + threadIdx.x;
        if (e < NE) atomicAdd(&deg[dst[e]], 1);
    } else {
        int t = (b - CB - DB) * 256 + threadIdx.x;
        if (t < 2 * 16 * 16 * 32) {
            int L    = t >> 13;
            int s    = (t >> 9) & 15;
            int n    = (t >> 5) & 15;
            int lane = t & 31;
            int gid = lane >> 2, tig = lane & 3;
            int col = n * 8 + gid;
            const float* Wl = L ? W2l : W1l;
            const float* Wr = L ? W2r : W1r;
            uint32_t bb[2];
#pragma unroll
            for (int r = 0; r < 2; r++) {
                int k0 = s * 16 + r * 8 + 2 * tig;
                float v0 = (k0     < 128) ? Wl[k0 * 128 + col]       : Wr[(k0 - 128) * 128 + col];
                float v1 = (k0 + 1 < 128) ? Wl[(k0 + 1) * 128 + col] : Wr[(k0 + 1 - 128) * 128 + col];
                __half2 p = __floats2half2_rn(v0, v1);
                bb[r] = *(uint32_t*)&p;
            }
            bf[t] = make_uint2(bb[0], bb[1]);
        }
    }
}

// ---------------- CSR build ---------------------------------------------------
__global__ void k_scan1(const int* __restrict__ deg, int* __restrict__ out,
                        int* __restrict__ bsums, int* __restrict__ cursor) {
    __shared__ int sh[1024];
    int gid = blockIdx.x * 1024 + threadIdx.x;
    int v = (gid < NN) ? deg[gid] : 0;
    sh[threadIdx.x] = v;
    __syncthreads();
#pragma unroll
    for (int off = 1; off < 1024; off <<= 1) {
        int t = (threadIdx.x >= off) ? sh[threadIdx.x - off] : 0;
        __syncthreads();
        sh[threadIdx.x] += t;
        __syncthreads();
    }
    if (gid < NN) {
        out[gid]    = sh[threadIdx.x] - v;
        cursor[gid] = 0;
    }
    if (threadIdx.x == 1023) bsums[blockIdx.x] = sh[1023];
}

__global__ void k_scan3f(int* __restrict__ out, const int* __restrict__ bsums, int nb) {
    __shared__ int sh[64];
    int t = threadIdx.x;
    if (t < 32) {
        int v0 = (t      < nb) ? bsums[t]      : 0;
        int v1 = (t + 32 < nb) ? bsums[t + 32] : 0;
#pragma unroll
        for (int off = 1; off < 32; off <<= 1) {
            int u0 = __shfl_up_sync(0xffffffffu, v0, off);
            int u1 = __shfl_up_sync(0xffffffffu, v1, off);
            if ((int)t >= off) { v0 += u0; v1 += u1; }
        }
        int tot0 = __shfl_sync(0xffffffffu, v0, 31);
        sh[t]      = v0;
        sh[t + 32] = v1 + tot0;
    }
    __syncthreads();
    int offv = (blockIdx.x == 0) ? 0 : sh[blockIdx.x - 1];
    int gid = blockIdx.x * 1024 + t;
    if (gid < NN) out[gid] += offv;
}

__global__ void k_fill(const int* __restrict__ src, const int* __restrict__ dst,
                       const int* __restrict__ rowptr, int* __restrict__ cursor,
                       int* __restrict__ col) {
    int e = blockIdx.x * blockDim.x + threadIdx.x;
    if (e >= NE) return;
    int d = dst[e];
    int pos = rowptr[d] + atomicAdd(&cursor[d], 1);
    col[pos] = src[e];
}

// ---------------- mean aggregation (warp per node, fp16 in/out) --------------
__global__ void k_agg(const __half* __restrict__ h16,
                      const int* __restrict__ rowptr,
                      const int* __restrict__ deg,
                      const int* __restrict__ col,
                      __half* __restrict__ mean16) {
    int w    = (blockIdx.x * blockDim.x + threadIdx.x) >> 5;
    int lane = threadIdx.x & 31;
    if (w >= NN) return;
    int start = rowptr[w];
    int n     = deg[w];
    float4 acc = make_float4(0.f, 0.f, 0.f, 0.f);
    const uint2* hp = (const uint2*)h16;
    int j = 0;
    for (; j + 4 <= n; j += 4) {
        int s0 = col[start + j];
        int s1 = col[start + j + 1];
        int s2 = col[start + j + 2];
        int s3 = col[start + j + 3];
        uint2 r0 = hp[(long)s0 * 32 + lane];
        uint2 r1 = hp[(long)s1 * 32 + lane];
        uint2 r2 = hp[(long)s2 * 32 + lane];
        uint2 r3 = hp[(long)s3 * 32 + lane];
#pragma unroll
        for (int u = 0; u < 4; u++) {
            uint2 raw = (u == 0) ? r0 : (u == 1) ? r1 : (u == 2) ? r2 : r3;
            float2 a = __half22float2(*(const __half2*)&raw.x);
            float2 b = __half22float2(*(const __half2*)&raw.y);
            acc.x += a.x; acc.y += a.y; acc.z += b.x; acc.w += b.y;
        }
    }
    for (; j < n; j++) {
        int s = col[start + j];
        uint2 raw = hp[(long)s * 32 + lane];
        float2 a = __half22float2(*(const __half2*)&raw.x);
        float2 b = __half22float2(*(const __half2*)&raw.y);
        acc.x += a.x; acc.y += a.y; acc.z += b.x; acc.w += b.y;
    }
    float inv = 1.0f / fmaxf((float)n, 1.0f);
    __half2 p0 = __floats2half2_rn(acc.x * inv, acc.y * inv);
    __half2 p1 = __floats2half2_rn(acc.z * inv, acc.w * inv);
    uint2 pk = make_uint2(*(uint32_t*)&p0, *(uint32_t*)&p1);
    *(uint2*)&mean16[(long)w * 128 + lane * 4] = pk;
}

// ---------------- mma.sync fp16 GEMM (single-term, exact fp16 A) -------------
// out[M,128] = [mean16|h16](K=256, fp16) @ Wfp16 + b
#define APITCH 40                      // halfwords per row
#define PLANE  (128 * APITCH * 2)      // 10240 bytes

__global__ void __launch_bounds__(256, 1)
k_gemm_mma(const __half* __restrict__ Mean16, const __half* __restrict__ H16,
           const uint2* __restrict__ Bf, const float* __restrict__ bias,
           __half* __restrict__ outh, int do_relu) {
    __shared__ __align__(16) uint8_t sA[2][PLANE];

    int tid  = threadIdx.x;
    int wid  = tid >> 5;
    int lane = tid & 31;
    int wm   = wid & 3;
    int wn   = wid >> 2;
    int gid  = lane >> 2, tig = lane & 3;
    int row0 = blockIdx.x * 128;

    int laneRow = lane & 15;
    int laneKo  = (lane >> 4) * 8;

    uint32_t sbase = su32(&sA[0][0]);

    float acc[2][8][4];
#pragma unroll
    for (int mt = 0; mt < 2; mt++)
#pragma unroll
        for (int nt = 0; nt < 8; nt++)
#pragma unroll
            for (int j = 0; j < 4; j++) acc[mt][nt][j] = 0.f;

    const uint4 z4 = make_uint4(0u, 0u, 0u, 0u);
    int srow = tid >> 1;          // staging row (0..127)
    int sseg = tid & 1;           // 16-half segment (0/1)

    // ---- stage chunk 0 (k 0..31 of mean16) ----
    {
        int gr = row0 + srow;
        uint4 v0 = z4, v1 = z4;
        if (gr < NN) {
            const uint4* src = (const uint4*)&Mean16[(long)gr * 128 + sseg * 16];
            v0 = src[0];
            v1 = src[1];
        }
        int off = srow * (APITCH * 2) + sseg * 32;
        *(uint4*)&sA[0][off]      = v0;
        *(uint4*)&sA[0][off + 16] = v1;
    }

#pragma unroll 1
    for (int c = 0; c < 8; ++c) {
        __syncthreads();

        // prefetch next chunk
        uint4 p0 = z4, p1 = z4;
        if (c < 7) {
            const __half* Asrc = (c + 1 < 4) ? Mean16 : H16;
            int bk = ((c + 1) & 3) * 32;
            int gr = row0 + srow;
            if (gr < NN) {
                const uint4* src = (const uint4*)&Asrc[(long)gr * 128 + bk + sseg * 16];
                p0 = src[0];
                p1 = src[1];
            }
        }

        uint32_t aBase = sbase + (uint32_t)((c & 1) * PLANE);
#pragma unroll
        for (int ks = 0; ks < 2; ks++) {
            int s = c * 2 + ks;
            uint32_t af[2][4];
#pragma unroll
            for (int mt = 0; mt < 2; mt++) {
                uint32_t addr = aBase
                    + (uint32_t)((wm * 32 + mt * 16 + laneRow) * (APITCH * 2)
                                 + (ks * 16 + laneKo) * 2);
                LDSM4(af[mt], addr);
            }
            uint2 bf[8];
#pragma unroll
            for (int nt = 0; nt < 8; nt++)
                bf[nt] = __ldg(&Bf[(s * 16 + wn * 8 + nt) * 32 + lane]);
#pragma unroll
            for (int nt = 0; nt < 8; nt++) {
                uint32_t bb[2] = {bf[nt].x, bf[nt].y};
#pragma unroll
                for (int mt = 0; mt < 2; mt++)
                    MMA_F16(acc[mt][nt], af[mt], bb);
            }
        }

        // store prefetched chunk into other buffer
        if (c < 7) {
            int nb = (c + 1) & 1;
            int off = srow * (APITCH * 2) + sseg * 32;
            *(uint4*)&sA[nb][off]      = p0;
            *(uint4*)&sA[nb][off + 16] = p1;
        }
    }

    // ---- epilogue: fp16 out ----
#pragma unroll
    for (int mt = 0; mt < 2; mt++) {
        int r0 = row0 + wm * 32 + mt * 16 + gid;
        int r1 = r0 + 8;
#pragma unroll
        for (int nt = 0; nt < 8; nt++) {
            int cbase = wn * 64 + nt * 8 + tig * 2;
            float bx = __ldg(&bias[cbase]);
            float by = __ldg(&bias[cbase + 1]);
            float2 v0 = make_float2(acc[mt][nt][0] + bx, acc[mt][nt][1] + by);
            float2 v1 = make_float2(acc[mt][nt][2] + bx, acc[mt][nt][3] + by);
            if (do_relu) {
                v0.x = fmaxf(v0.x, 0.f); v0.y = fmaxf(v0.y, 0.f);
                v1.x = fmaxf(v1.x, 0.f); v1.y = fmaxf(v1.y, 0.f);
            }
            __half2 h0p = __floats2half2_rn(v0.x, v0.y);
            __half2 h1p = __floats2half2_rn(v1.x, v1.y);
            if (r0 < NN) *(uint32_t*)&outh[(long)r0 * 128 + cbase] = *(uint32_t*)&h0p;
            if (r1 < NN) *(uint32_t*)&outh[(long)r1 * 128 + cbase] = *(uint32_t*)&h1p;
        }
    }
}

// ---------------- edge-wise dot product (fp16 gather) -------------------------
__global__ void k_edgedot(const __half* __restrict__ h16,
                          const int* __restrict__ eli,
                          float* __restrict__ out) {
    int w    = (blockIdx.x * blockDim.x + threadIdx.x) >> 5;
    int lane = threadIdx.x & 31;
    if (w >= NL) return;
    int s = eli[w];
    int d = eli[NL + w];
    const uint2* hp = (const uint2*)h16;
    uint2 ra = hp[(long)s * 32 + lane];
    uint2 rb = hp[(long)d * 32 + lane];
    float2 a0 = __half22float2(*(const __half2*)&ra.x);
    float2 a1 = __half22float2(*(const __half2*)&ra.y);
    float2 b0 = __half22float2(*(const __half2*)&rb.x);
    float2 b1 = __half22float2(*(const __half2*)&rb.y);
    float sum = a0.x * b0.x + a0.y * b0.y + a1.x * b1.x + a1.y * b1.y;
#pragma unroll
    for (int o = 16; o; o >>= 1) sum += __shfl_xor_sync(0xffffffffu, sum, o);
    if (lane == 0) out[w] = sum;
}

// ---------------- launch ------------------------------------------------------
extern "C" void kernel_launch(void* const* d_in, const int* in_sizes, int n_in,
                              void* d_out, int out_size) {
    const int*   n_id = (const int*)d_in[0];
    const float* x    = (const float*)d_in[1];
    const int*   ei   = (const int*)d_in[2];
    const int*   eli  = (const int*)d_in[3];
    const float* emb  = (const float*)d_in[4];
    const float* W1l  = (const float*)d_in[5];
    const float* W1r  = (const float*)d_in[6];
    const float* b1   = (const float*)d_in[7];
    const float* W2l  = (const float*)d_in[8];
    const float* W2r  = (const float*)d_in[9];
    const float* b2   = (const float*)d_in[10];
    float* out = (float*)d_out;

    __half *h0h, *mean16, *h1h, *h2h;
    int *deg, *rowptr, *cursor, *col, *bsums;
    uint2* bfrag;
    cudaGetSymbolAddress((void**)&h0h,    g_h0h);
    cudaGetSymbolAddress((void**)&mean16, g_mean16);
    cudaGetSymbolAddress((void**)&h1h,    g_h1h);
    cudaGetSymbolAddress((void**)&h2h,    g_h2h);
    cudaGetSymbolAddress((void**)&deg,    g_deg);
    cudaGetSymbolAddress((void**)&rowptr, g_rowptr);
    cudaGetSymbolAddress((void**)&cursor, g_cursor);
    cudaGetSymbolAddress((void**)&col,    g_col);
    cudaGetSymbolAddress((void**)&bsums,  g_bsums);
    cudaGetSymbolAddress((void**)&bfrag,  g_bfrag);

    const int NB_SCAN = (NN + 1023) / 1024;  // 49

    cudaMemsetAsync(deg, 0, sizeof(int) * NN);

    // fused prologue: concat(fp16) + degree + W fp16 fragments
    k_pre<<<CB + DB + WB, 256>>>(n_id, x, emb, ei + NE, W1l, W1r, W2l, W2r,
                                 h0h, deg, bfrag);
    k_scan1<<<NB_SCAN, 1024>>>(deg, rowptr, bsums, cursor);
    k_scan3f<<<NB_SCAN, 1024>>>(rowptr, bsums, NB_SCAN);
    k_fill<<<(NE + 255) / 256, 256>>>(ei, ei + NE, rowptr, cursor, col);

    const int GB = (NN + 127) / 128;  // 391

    // layer 1
    k_agg<<<(NN * 32 + 255) / 256, 256>>>(h0h, rowptr, deg, col, mean16);
    k_gemm_mma<<<GB, 256>>>(mean16, h0h, bfrag, b1, h1h, 1);

    // layer 2
    k_agg<<<(NN * 32 + 255) / 256, 256>>>(h1h, rowptr, deg, col, mean16);
    k_gemm_mma<<<GB, 256>>>(mean16, h1h, bfrag + 8192, b2, h2h, 0);

    // classifier
    k_edgedot<<<(NL * 32 + 255) / 256, 256>>>(h2h, eli, out);
}